// round 5
// baseline (speedup 1.0000x reference)
#include <cuda_runtime.h>
#include <cstdint>

// Problem shape (fixed dataset): preds (16,2048,78) f32, targets (16,32,78) f32,
// masks (16,32) bool (encoding sniffed), img_w=800. Output: concat(assigned_mask,
// matched) cast to FLOAT32, 2*B*P elements.

#define BB 16
#define PP 2048
#define GG 32
#define DD 78
#define NN 72
#define QQ 10

// Scratch (device globals; no allocation allowed)
__device__ float g_cost[BB * GG * PP];    // 4 MB, layout [b][g][p]
__device__ float g_iou [BB * GG * PP];    // 4 MB
__device__ int   g_selk[BB * GG];
__device__ int   g_selidx[BB * GG * QQ];
__device__ float g_selcost[BB * GG * QQ];
__device__ float g_mask[BB * GG];         // decoded masks as 0.0/1.0

// ---------------------------------------------------------------------------
// Kernel 0: decode masks regardless of dtype encoding.
//   int8 all-true -> word0 = 0x01010101 ; int32 true -> 0x00000001 ;
//   float32 1.0f  -> 0x3F800000. Word path only for 4-byte encodings (no OOB).
// ---------------------------------------------------------------------------
__global__ void mask_decode_kernel(const unsigned char* __restrict__ m)
{
    __shared__ int enc;  // 0 = 1-byte elements, 1 = 4-byte elements
    if (threadIdx.x == 0) {
        unsigned int w0 = *(const unsigned int*)m;
        enc = (w0 == 1u || w0 == 0x3F800000u) ? 1 : 0;
    }
    __syncthreads();
    int i = threadIdx.x;           // blockDim.x == BB*GG == 512
    bool t;
    if (enc) t = ((const unsigned int*)m)[i] != 0u;   // int32 or float32 nonzero
    else     t = m[i] != 0;                           // byte bool
    g_mask[i] = t ? 1.0f : 0.0f;
}

// ---------------------------------------------------------------------------
// Kernel 1: pairwise cost + iou.
//   cls  = -log(clip(softmax(preds[:2])[1], 1e-8))
//   reg  = |p3-t3| + |p2-t2| + |p4-t4|
//   iou  = (30*nv - S) / (30*nv + S + 1e-9),  S = sum_valid |pred_n - gt_n| (pixels)
//   iouc = mask ? -log(clip(iou*mask, 1e-8)) : 0
//   total = 3*cls + 3*reg + 3*iouc + 1e5*(1-mask)
// One thread per prior; gt tile for this batch staged in smem.
// ---------------------------------------------------------------------------
__global__ __launch_bounds__(128) void cost_kernel(
    const float* __restrict__ preds,
    const float* __restrict__ targets,
    const int* __restrict__ imgw_p)
{
    const int b = blockIdx.y;
    const int p = blockIdx.x * 128 + threadIdx.x;

    // robust scalar decode: int32/int64 little-endian, or float32 bits
    int iw = imgw_p ? *imgw_p : 800;
    if (iw <= 0 || iw > 100000) {
        float fw = imgw_p ? __int_as_float(iw) : 800.0f;
        iw = (fw >= 1.0f && fw <= 100000.0f) ? (int)fw : 800;
    }
    const float img_w = (float)iw;
    const float scale = img_w - 1.0f;

    __shared__ float2 s_gv[GG][NN];   // .x = scaled gt point, .y = valid flag
    __shared__ float  s_t2[GG], s_t3[GG], s_t4[GG];
    __shared__ float  s_nv30[GG];
    __shared__ float  s_m[GG];

    for (int idx = threadIdx.x; idx < GG * DD; idx += 128) {
        int g = idx / DD, d = idx % DD;
        float v = targets[((size_t)b * GG + g) * DD + d];
        if (d == 2)      s_t2[g] = v;
        else if (d == 3) s_t3[g] = v;
        else if (d == 4) s_t4[g] = v;
        if (d >= 6) {
            float x = v * scale;
            bool inval = (x < 0.0f) || (x >= img_w);
            s_gv[g][d - 6] = make_float2(x, inval ? 0.0f : 1.0f);
        }
    }
    for (int g = threadIdx.x; g < GG; g += 128)
        s_m[g] = g_mask[b * GG + g];
    __syncthreads();
    if (threadIdx.x < GG) {
        float nv = 0.0f;
        for (int n = 0; n < NN; n++) nv += s_gv[threadIdx.x][n].y;
        s_nv30[threadIdx.x] = 30.0f * nv;
    }
    __syncthreads();

    const float* row = preds + ((size_t)b * PP + p) * DD;
    float pr0 = row[0], pr1 = row[1], pr2 = row[2], pr3 = row[3], pr4 = row[4];
    float line[NN];
#pragma unroll
    for (int n = 0; n < NN; n++) line[n] = row[6 + n] * scale;

    float mx = fmaxf(pr0, pr1);
    float e0 = expf(pr0 - mx), e1 = expf(pr1 - mx);
    float p1 = e1 / (e0 + e1);
    float cls3 = -3.0f * logf(fmaxf(p1, 1e-8f));

    for (int g = 0; g < GG; g++) {
        float S = 0.0f;
#pragma unroll
        for (int n = 0; n < NN; n++) {
            float2 gv = s_gv[g][n];
            S = fmaf(gv.y, fabsf(line[n] - gv.x), S);
        }
        float nv30 = s_nv30[g];
        float iou = (nv30 - S) / (nv30 + S + 1e-9f);
        float m = s_m[g];
        iou = iou * m;
        float reg = fabsf(pr3 - s_t3[g]) + fabsf(pr2 - s_t2[g]) + fabsf(pr4 - s_t4[g]);
        float iouc = (m > 0.0f) ? -logf(fmaxf(iou, 1e-8f)) : 0.0f;
        float total = cls3 + 3.0f * reg + 3.0f * iouc + 1e5f * (1.0f - m);
        size_t o = ((size_t)(b * GG + g)) * PP + p;
        g_cost[o] = total;
        g_iou[o]  = iou;
    }
}

// ---------------------------------------------------------------------------
// Kernel 2: per-(b,g) selection.
//   k = clip((int)(sum of top-10 iou over priors), 1, P)   (k <= 9 since iou < 1)
//   candidates = k smallest costs under lexicographic (cost, index)
//               == {p : stable-argsort rank < k} in the reference.
// Per-thread register top-10 via compare-swap chain, then smem tree merge.
// ---------------------------------------------------------------------------
__device__ __forceinline__ unsigned int fkey(float f) {
    unsigned int u = __float_as_uint(f);
    return (u & 0x80000000u) ? ~u : (u | 0x80000000u);  // total order as uint
}
__device__ __forceinline__ float fkey_inv(unsigned int k) {
    unsigned int u = (k & 0x80000000u) ? (k & 0x7FFFFFFFu) : ~k;
    return __uint_as_float(u);
}

__global__ __launch_bounds__(256) void select_kernel()
{
    const int bg = blockIdx.x;
    const float* crow = g_cost + (size_t)bg * PP;
    const float* irow = g_iou  + (size_t)bg * PP;
    const int tid = threadIdx.x;

    float ti[QQ];                 // descending top-10 iou
    unsigned long long tc[QQ];    // ascending bottom-10 (cost,idx) keys
#pragma unroll
    for (int j = 0; j < QQ; j++) { ti[j] = -3.4e38f; tc[j] = 0xFFFFFFFFFFFFFFFFull; }

    for (int p = tid; p < PP; p += 256) {
        float v = irow[p];
#pragma unroll
        for (int j = 0; j < QQ; j++) {
            if (v > ti[j]) { float t = ti[j]; ti[j] = v; v = t; }
        }
        unsigned long long key =
            ((unsigned long long)fkey(crow[p]) << 32) | (unsigned int)p;
#pragma unroll
        for (int j = 0; j < QQ; j++) {
            if (key < tc[j]) { unsigned long long t = tc[j]; tc[j] = key; key = t; }
        }
    }

    __shared__ float s_i[256][QQ];
    __shared__ unsigned long long s_c[256][QQ];
#pragma unroll
    for (int j = 0; j < QQ; j++) { s_i[tid][j] = ti[j]; s_c[tid][j] = tc[j]; }
    __syncthreads();

    for (int stride = 128; stride >= 1; stride >>= 1) {
        if (tid < stride) {
            float oi[QQ]; unsigned long long oc[QQ];
            int i = 0, j = 0;
#pragma unroll
            for (int t = 0; t < QQ; t++) {           // i + j == t < 10, both in range
                float av = s_i[tid][i], bv = s_i[tid + stride][j];
                if (av >= bv) { oi[t] = av; i++; } else { oi[t] = bv; j++; }
            }
            i = 0; j = 0;
#pragma unroll
            for (int t = 0; t < QQ; t++) {
                unsigned long long av = s_c[tid][i], bv = s_c[tid + stride][j];
                if (av <= bv) { oc[t] = av; i++; } else { oc[t] = bv; j++; }
            }
#pragma unroll
            for (int t = 0; t < QQ; t++) { s_i[tid][t] = oi[t]; s_c[tid][t] = oc[t]; }
        }
        __syncthreads();
    }

    if (tid == 0) {
        float sum = 0.0f;
        for (int j = 0; j < QQ; j++) sum += s_i[0][j];   // descending order == top_k order
        int k = (int)sum;            // astype(int32): truncate toward zero
        if (k < 1)  k = 1;           // clip(., 1, P)
        if (k > QQ) k = QQ;          // cannot exceed 10 (each iou < 1)
        if (g_mask[bg] == 0.0f) k = 0;  // invalid gt selects nothing
        g_selk[bg] = k;
        for (int j = 0; j < k; j++) {
            unsigned long long key = s_c[0][j];
            g_selidx[bg * QQ + j]  = (int)(key & 0xFFFFFFFFull);
            g_selcost[bg * QQ + j] = fkey_inv((unsigned int)(key >> 32));
        }
    }
}

// ---------------------------------------------------------------------------
// Kernel 3: sequential per-gt assignment with min-cost conflict resolution.
// One CTA per batch; matched/minc live in smem. Within one g the <=10 selected
// priors are distinct, so parallel updates are race-free; sync between g's.
// OUTPUT IS FLOAT32: mask in {0,1}, matched in {-1..31} (exactly representable).
// ---------------------------------------------------------------------------
__global__ __launch_bounds__(256) void assign_kernel(float* __restrict__ out)
{
    const int b = blockIdx.x;
    __shared__ float minc[PP];
    __shared__ int   matched[PP];
    for (int p = threadIdx.x; p < PP; p += 256) { minc[p] = 1e8f; matched[p] = -1; }
    __syncthreads();

    for (int g = 0; g < GG; g++) {
        int bg = b * GG + g;
        int k = g_selk[bg];
        if ((int)threadIdx.x < k) {
            int   p = g_selidx[bg * QQ + threadIdx.x];
            float c = g_selcost[bg * QQ + threadIdx.x];
            if (c < minc[p]) { matched[p] = g; minc[p] = c; }
        }
        __syncthreads();
    }

    for (int p = threadIdx.x; p < PP; p += 256) {
        int m = matched[p];
        out[(size_t)b * PP + p] = (m >= 0) ? 1.0f : 0.0f;             // assigned_mask
        out[(size_t)BB * PP + (size_t)b * PP + p] = (float)m;         // matched
    }
}

// ---------------------------------------------------------------------------
extern "C" void kernel_launch(void* const* d_in, const int* in_sizes, int n_in,
                              void* d_out, int out_size)
{
    const float* preds   = (const float*)d_in[0];
    const float* targets = (const float*)d_in[1];
    const unsigned char* masks = (const unsigned char*)d_in[2];
    const int* imgw = (n_in > 3) ? (const int*)d_in[3] : nullptr;

    mask_decode_kernel<<<1, BB * GG>>>(masks);
    cost_kernel<<<dim3(PP / 128, BB), 128>>>(preds, targets, imgw);
    select_kernel<<<BB * GG, 256>>>();
    assign_kernel<<<BB, 256>>>((float*)d_out);
}

// round 6
// speedup vs baseline: 1.2288x; 1.2288x over previous
#include <cuda_runtime.h>
#include <cstdint>

// Problem shape (fixed dataset): preds (16,2048,78) f32, targets (16,32,78) f32,
// masks (16,32) bool (encoding sniffed), img_w=800. Output: concat(assigned_mask,
// matched) as FLOAT32, 2*B*P elements.

#define BB 16
#define PP 2048
#define GG 32
#define DD 78
#define NN 72
#define QI 10   // top-k depth for iou (SIMOTA_Q)
#define QC 9    // candidate depth for cost (k <= 9 provable: each iou < 1)

// Scratch (device globals; no allocation allowed)
__device__ float g_cost[BB * GG * PP];               // 4 MB, layout [b][g][p]
__device__ float g_iou [BB * GG * PP];               // 4 MB
__device__ unsigned long long g_akey[BB * PP];       // packed (fkey(cost)<<32)|g

// mask decode helper: sniff element width from word0.
//   byte bool all-true -> 0x01010101 ; int32 true -> 0x00000001 ; f32 1.0 -> 0x3F800000
__device__ __forceinline__ int mask_is_word(const unsigned char* m) {
    unsigned int w0 = *(const unsigned int*)m;
    return (w0 == 1u || w0 == 0x3F800000u) ? 1 : 0;
}
__device__ __forceinline__ bool mask_at(const unsigned char* m, int enc, int i) {
    return enc ? (((const unsigned int*)m)[i] != 0u) : (m[i] != 0);
}

__device__ __forceinline__ unsigned int fkey(float f) {
    unsigned int u = __float_as_uint(f);
    return (u & 0x80000000u) ? ~u : (u | 0x80000000u);  // monotone total order
}

// ---------------------------------------------------------------------------
// Kernel 1: pairwise cost + iou; also initializes g_akey for this (b,p).
//   cls  = -log(clip(softmax(preds[:2])[1], 1e-8))
//   reg  = |p3-t3| + |p2-t2| + |p4-t4|
//   iou  = (30*nv - S) / (30*nv + S + 1e-9),  S = sum_valid |pred_n - gt_n| (pixels)
//   iouc = mask ? -log(clip(iou*mask, 1e-8)) : 0
//   total = 3*cls + 3*reg + 3*iouc + 1e5*(1-mask)
// ---------------------------------------------------------------------------
__global__ __launch_bounds__(128) void cost_kernel(
    const float* __restrict__ preds,
    const float* __restrict__ targets,
    const unsigned char* __restrict__ masks,
    const int* __restrict__ imgw_p)
{
    const int b = blockIdx.y;
    const int p = blockIdx.x * 128 + threadIdx.x;

    // robust scalar decode: int32/int64 little-endian, or float32 bits
    int iw = imgw_p ? *imgw_p : 800;
    if (iw <= 0 || iw > 100000) {
        float fw = imgw_p ? __int_as_float(iw) : 800.0f;
        iw = (fw >= 1.0f && fw <= 100000.0f) ? (int)fw : 800;
    }
    const float img_w = (float)iw;
    const float scale = img_w - 1.0f;

    __shared__ float2 s_gv[GG][NN];   // .x = scaled gt point, .y = valid flag
    __shared__ float  s_t2[GG], s_t3[GG], s_t4[GG];
    __shared__ float  s_nv30[GG];
    __shared__ float  s_m[GG];

    for (int idx = threadIdx.x; idx < GG * DD; idx += 128) {
        int g = idx / DD, d = idx % DD;
        float v = targets[((size_t)b * GG + g) * DD + d];
        if (d == 2)      s_t2[g] = v;
        else if (d == 3) s_t3[g] = v;
        else if (d == 4) s_t4[g] = v;
        if (d >= 6) {
            float x = v * scale;
            bool inval = (x < 0.0f) || (x >= img_w);
            s_gv[g][d - 6] = make_float2(x, inval ? 0.0f : 1.0f);
        }
    }
    if (threadIdx.x < GG) {
        int enc = mask_is_word(masks);
        s_m[threadIdx.x] = mask_at(masks, enc, b * GG + threadIdx.x) ? 1.0f : 0.0f;
    }
    __syncthreads();
    if (threadIdx.x < GG) {
        float nv = 0.0f;
        for (int n = 0; n < NN; n++) nv += s_gv[threadIdx.x][n].y;
        s_nv30[threadIdx.x] = 30.0f * nv;
    }
    __syncthreads();

    // init assignment key for this prior (select_kernel atomics come later in stream)
    g_akey[b * PP + p] = 0xFFFFFFFFFFFFFFFFull;

    const float* row = preds + ((size_t)b * PP + p) * DD;
    float pr0 = row[0], pr1 = row[1], pr2 = row[2], pr3 = row[3], pr4 = row[4];
    float line[NN];
#pragma unroll
    for (int n = 0; n < NN; n++) line[n] = row[6 + n] * scale;

    float mx = fmaxf(pr0, pr1);
    float e0 = expf(pr0 - mx), e1 = expf(pr1 - mx);
    float p1 = e1 / (e0 + e1);
    float cls3 = -3.0f * logf(fmaxf(p1, 1e-8f));

    for (int g = 0; g < GG; g++) {
        float S = 0.0f;
#pragma unroll
        for (int n = 0; n < NN; n++) {
            float2 gv = s_gv[g][n];
            S = fmaf(gv.y, fabsf(line[n] - gv.x), S);
        }
        float nv30 = s_nv30[g];
        float iou = (nv30 - S) / (nv30 + S + 1e-9f);
        float m = s_m[g];
        iou = iou * m;
        float reg = fabsf(pr3 - s_t3[g]) + fabsf(pr2 - s_t2[g]) + fabsf(pr4 - s_t4[g]);
        float iouc = (m > 0.0f) ? -logf(fmaxf(iou, 1e-8f)) : 0.0f;
        float total = cls3 + 3.0f * reg + 3.0f * iouc + 1e5f * (1.0f - m);
        size_t o = ((size_t)(b * GG + g)) * PP + p;
        g_cost[o] = total;
        g_iou[o]  = iou;
    }
}

// ---------------------------------------------------------------------------
// Kernel 2: per-(b,g) selection + assignment scatter.
//   k = clip((int)(sum of top-10 iou over priors), 1, P)   (k <= 9 since iou < 1)
//   candidates = k smallest costs under lexicographic (cost, index)
//               == {p : stable-argsort rank < k} in the reference.
//   Final assignment per prior = lexicographic min over (cost, g) among gts
//   selecting it (strict-< update keeps earliest g on ties) -> atomicMin of
//   packed key (fkey(cost)<<32 | g). Order-independent => scatter here.
// ---------------------------------------------------------------------------
__global__ __launch_bounds__(256) void select_kernel(const unsigned char* __restrict__ masks)
{
    const int bg = blockIdx.x;
    const float* crow = g_cost + (size_t)bg * PP;
    const float* irow = g_iou  + (size_t)bg * PP;
    const int tid = threadIdx.x;

    float ti[QI];                 // descending top-10 iou
    unsigned long long tc[QC];    // ascending bottom-9 (cost,idx) keys
#pragma unroll
    for (int j = 0; j < QI; j++) ti[j] = -3.4e38f;
#pragma unroll
    for (int j = 0; j < QC; j++) tc[j] = 0xFFFFFFFFFFFFFFFFull;

    for (int p = tid; p < PP; p += 256) {
        float v = __ldg(irow + p);
#pragma unroll
        for (int j = 0; j < QI; j++) {
            if (v > ti[j]) { float t = ti[j]; ti[j] = v; v = t; }
        }
        unsigned long long key =
            ((unsigned long long)fkey(__ldg(crow + p)) << 32) | (unsigned int)p;
#pragma unroll
        for (int j = 0; j < QC; j++) {
            if (key < tc[j]) { unsigned long long t = tc[j]; tc[j] = key; key = t; }
        }
    }

    __shared__ float s_i[256][QI];
    __shared__ unsigned long long s_c[256][QC];
#pragma unroll
    for (int j = 0; j < QI; j++) s_i[tid][j] = ti[j];
#pragma unroll
    for (int j = 0; j < QC; j++) s_c[tid][j] = tc[j];
    __syncthreads();

    for (int stride = 128; stride >= 1; stride >>= 1) {
        if (tid < stride) {
            float oi[QI]; unsigned long long oc[QC];
            int i = 0, j = 0;
#pragma unroll
            for (int t = 0; t < QI; t++) {           // i + j == t < QI, both in range
                float av = s_i[tid][i], bv = s_i[tid + stride][j];
                if (av >= bv) { oi[t] = av; i++; } else { oi[t] = bv; j++; }
            }
            i = 0; j = 0;
#pragma unroll
            for (int t = 0; t < QC; t++) {
                unsigned long long av = s_c[tid][i], bv = s_c[tid + stride][j];
                if (av <= bv) { oc[t] = av; i++; } else { oc[t] = bv; j++; }
            }
#pragma unroll
            for (int t = 0; t < QI; t++) s_i[tid][t] = oi[t];
#pragma unroll
            for (int t = 0; t < QC; t++) s_c[tid][t] = oc[t];
        }
        __syncthreads();
    }

    if (tid == 0) {
        float sum = 0.0f;
        for (int j = 0; j < QI; j++) sum += s_i[0][j];   // descending == top_k order
        int k = (int)sum;            // astype(int32): truncate toward zero
        if (k < 1)  k = 1;           // clip(., 1, P)
        if (k > QC) k = QC;          // provably <= 9
        int enc = mask_is_word(masks);
        if (!mask_at(masks, enc, bg)) k = 0;   // invalid gt selects nothing
        int b = bg / GG;
        unsigned int g = (unsigned int)(bg % GG);
        for (int j = 0; j < k; j++) {
            unsigned long long key = s_c[0][j];
            int p = (int)(key & 0xFFFFFFFFull);
            unsigned int ck = (unsigned int)(key >> 32);
            if (ck != 0xFFFFFFFFu) {  // guard: sentinel / cost>=1e8 never assigns
                unsigned long long akey = ((unsigned long long)ck << 32) | g;
                atomicMin(&g_akey[b * PP + p], akey);   // fire-and-forget RED
            }
        }
    }
}

// ---------------------------------------------------------------------------
// Kernel 3: fully-parallel output writer.
//   key == MAX  -> unmatched: mask 0, matched -1
//   else        -> matched g = low 32 bits of key
// ---------------------------------------------------------------------------
__global__ __launch_bounds__(256) void output_kernel(float* __restrict__ out)
{
    int i = blockIdx.x * 256 + threadIdx.x;        // i in [0, BB*PP)
    unsigned long long key = g_akey[i];
    bool matched = (key != 0xFFFFFFFFFFFFFFFFull);
    int g = (int)(key & 0xFFFFFFFFull);
    out[i] = matched ? 1.0f : 0.0f;                        // assigned_mask
    out[BB * PP + i] = matched ? (float)g : -1.0f;         // matched
}

// ---------------------------------------------------------------------------
extern "C" void kernel_launch(void* const* d_in, const int* in_sizes, int n_in,
                              void* d_out, int out_size)
{
    const float* preds   = (const float*)d_in[0];
    const float* targets = (const float*)d_in[1];
    const unsigned char* masks = (const unsigned char*)d_in[2];
    const int* imgw = (n_in > 3) ? (const int*)d_in[3] : nullptr;

    cost_kernel<<<dim3(PP / 128, BB), 128>>>(preds, targets, masks, imgw);
    select_kernel<<<BB * GG, 256>>>(masks);
    output_kernel<<<(BB * PP) / 256, 256>>>((float*)d_out);
}

// round 8
// speedup vs baseline: 1.2634x; 1.0282x over previous
#include <cuda_runtime.h>
#include <cstdint>

// Problem shape (fixed dataset): preds (16,2048,78) f32, targets (16,32,78) f32,
// masks (16,32) bool (encoding sniffed), img_w=800. Output: concat(assigned_mask,
// matched) as FLOAT32, 2*B*P elements.

#define BB 16
#define PP 2048
#define GG 32
#define DD 78
#define NN 72
#define QI 10   // top-k depth for iou (SIMOTA_Q)
#define QC 9    // candidate depth for cost (k <= 9 provable: each iou < 1)
#define GZ 4    // z-slices of the gt loop
#define GPB (GG / GZ)   // gts per block = 8

// Scratch (device globals; no allocation allowed)
__device__ float2 g_ci[BB * GG * PP];                // 8 MB: (.x=cost, .y=iou), [b][g][p]
__device__ unsigned long long g_akey[BB * PP];       // packed (fkey(cost)<<32)|g

// mask decode helper: sniff element width from word0.
//   byte bool all-true -> 0x01010101 ; int32 true -> 0x00000001 ; f32 1.0 -> 0x3F800000
__device__ __forceinline__ int mask_is_word(const unsigned char* m) {
    unsigned int w0 = *(const unsigned int*)m;
    return (w0 == 1u || w0 == 0x3F800000u) ? 1 : 0;
}
__device__ __forceinline__ bool mask_at(const unsigned char* m, int enc, int i) {
    return enc ? (((const unsigned int*)m)[i] != 0u) : (m[i] != 0);
}

__device__ __forceinline__ unsigned int fkey(float f) {
    unsigned int u = __float_as_uint(f);
    return (u & 0x80000000u) ? ~u : (u | 0x80000000u);  // monotone total order
}

// ---------------------------------------------------------------------------
// Kernel 1: pairwise cost + iou; z-slice of 8 gts per CTA for occupancy.
//   cls  = -log(clip(softmax(preds[:2])[1], 1e-8))
//   reg  = |p3-t3| + |p2-t2| + |p4-t4|
//   iou  = (30*nv - S) / (30*nv + S + 1e-9),  S = sum_valid |pred_n - gt_n| (pixels)
//   iouc = mask ? -log(clip(iou*mask, 1e-8)) : 0
//   total = 3*cls + 3*reg + 3*iouc + 1e5*(1-mask)
// ---------------------------------------------------------------------------
__global__ __launch_bounds__(128) void cost_kernel(
    const float* __restrict__ preds,
    const float* __restrict__ targets,
    const unsigned char* __restrict__ masks,
    const int* __restrict__ imgw_p)
{
    const int b = blockIdx.y;
    const int p = blockIdx.x * 128 + threadIdx.x;
    const int g0 = blockIdx.z * GPB;

    // robust scalar decode: int32/int64 little-endian, or float32 bits
    int iw = imgw_p ? *imgw_p : 800;
    if (iw <= 0 || iw > 100000) {
        float fw = imgw_p ? __int_as_float(iw) : 800.0f;
        iw = (fw >= 1.0f && fw <= 100000.0f) ? (int)fw : 800;
    }
    const float img_w = (float)iw;
    const float scale = img_w - 1.0f;

    __shared__ float2 s_gv[GPB][NN];  // .x = scaled gt point, .y = valid flag
    __shared__ float  s_t2[GPB], s_t3[GPB], s_t4[GPB];
    __shared__ float  s_nv30[GPB];
    __shared__ float  s_m[GPB];

    for (int idx = threadIdx.x; idx < GPB * DD; idx += 128) {
        int g = idx / DD, d = idx % DD;
        float v = targets[((size_t)b * GG + g0 + g) * DD + d];
        if (d == 2)      s_t2[g] = v;
        else if (d == 3) s_t3[g] = v;
        else if (d == 4) s_t4[g] = v;
        if (d >= 6) {
            float x = v * scale;
            bool inval = (x < 0.0f) || (x >= img_w);
            s_gv[g][d - 6] = make_float2(x, inval ? 0.0f : 1.0f);
        }
    }
    if (threadIdx.x < GPB) {
        int enc = mask_is_word(masks);
        s_m[threadIdx.x] = mask_at(masks, enc, b * GG + g0 + threadIdx.x) ? 1.0f : 0.0f;
    }
    __syncthreads();
    if (threadIdx.x < GPB) {
        float nv = 0.0f;
        for (int n = 0; n < NN; n++) nv += s_gv[threadIdx.x][n].y;
        s_nv30[threadIdx.x] = 30.0f * nv;
    }
    __syncthreads();

    // init assignment key once per (b,p)
    if (blockIdx.z == 0)
        g_akey[b * PP + p] = 0xFFFFFFFFFFFFFFFFull;

    const float* row = preds + ((size_t)b * PP + p) * DD;
    float pr0 = row[0], pr1 = row[1], pr2 = row[2], pr3 = row[3], pr4 = row[4];
    float line[NN];
#pragma unroll
    for (int n = 0; n < NN; n++) line[n] = row[6 + n] * scale;

    float mx = fmaxf(pr0, pr1);
    float e0 = expf(pr0 - mx), e1 = expf(pr1 - mx);
    float p1 = e1 / (e0 + e1);
    float cls3 = -3.0f * logf(fmaxf(p1, 1e-8f));

#pragma unroll
    for (int g = 0; g < GPB; g++) {
        float S = 0.0f;
#pragma unroll
        for (int n = 0; n < NN; n++) {
            float2 gv = s_gv[g][n];
            S = fmaf(gv.y, fabsf(line[n] - gv.x), S);
        }
        float nv30 = s_nv30[g];
        float iou = (nv30 - S) / (nv30 + S + 1e-9f);
        float m = s_m[g];
        iou = iou * m;
        float reg = fabsf(pr3 - s_t3[g]) + fabsf(pr2 - s_t2[g]) + fabsf(pr4 - s_t4[g]);
        float iouc = (m > 0.0f) ? -logf(fmaxf(iou, 1e-8f)) : 0.0f;
        float total = cls3 + 3.0f * reg + 3.0f * iouc + 1e5f * (1.0f - m);
        g_ci[((size_t)(b * GG + g0 + g)) * PP + p] = make_float2(total, iou);
    }
}

// ---------------------------------------------------------------------------
// Kernel 2: per-(b,g) selection + assignment scatter.
//   k = clip((int)(sum of top-10 iou over priors), 1, P)   (k <= 9 since iou < 1)
//   candidates = k smallest costs under lexicographic (cost, index)
//               == {p : stable-argsort rank < k} in the reference.
//   Final assignment per prior = lexicographic min over (cost, g) among gts
//   selecting it -> atomicMin of packed key (fkey(cost)<<32 | g).
// ---------------------------------------------------------------------------
__global__ __launch_bounds__(256) void select_kernel(const unsigned char* __restrict__ masks)
{
    const int bg = blockIdx.x;
    const float2* ci = g_ci + (size_t)bg * PP;
    const int tid = threadIdx.x;

    float ti[QI];                 // descending top-10 iou
    unsigned long long tc[QC];    // ascending bottom-9 (cost,idx) keys
#pragma unroll
    for (int j = 0; j < QI; j++) ti[j] = -3.4e38f;
#pragma unroll
    for (int j = 0; j < QC; j++) tc[j] = 0xFFFFFFFFFFFFFFFFull;

    for (int p = tid; p < PP; p += 256) {
        float2 v2 = __ldg(ci + p);
        float v = v2.y;
        if (v > ti[QI - 1]) {     // early skip: beats current worst?
#pragma unroll
            for (int j = 0; j < QI; j++) {
                if (v > ti[j]) { float t = ti[j]; ti[j] = v; v = t; }
            }
        }
        unsigned long long key =
            ((unsigned long long)fkey(v2.x) << 32) | (unsigned int)p;
        if (key < tc[QC - 1]) {   // early skip
#pragma unroll
            for (int j = 0; j < QC; j++) {
                if (key < tc[j]) { unsigned long long t = tc[j]; tc[j] = key; key = t; }
            }
        }
    }

    __shared__ float s_i[256][QI];
    __shared__ unsigned long long s_c[256][QC];
#pragma unroll
    for (int j = 0; j < QI; j++) s_i[tid][j] = ti[j];
#pragma unroll
    for (int j = 0; j < QC; j++) s_c[tid][j] = tc[j];
    __syncthreads();

    for (int stride = 128; stride >= 1; stride >>= 1) {
        if (tid < stride) {
            float oi[QI]; unsigned long long oc[QC];
            int i = 0, j = 0;
#pragma unroll
            for (int t = 0; t < QI; t++) {           // i + j == t, both in range
                float av = s_i[tid][i], bv = s_i[tid + stride][j];
                if (av >= bv) { oi[t] = av; i++; } else { oi[t] = bv; j++; }
            }
            i = 0; j = 0;
#pragma unroll
            for (int t = 0; t < QC; t++) {
                unsigned long long av = s_c[tid][i], bv = s_c[tid + stride][j];
                if (av <= bv) { oc[t] = av; i++; } else { oc[t] = bv; j++; }
            }
#pragma unroll
            for (int t = 0; t < QI; t++) s_i[tid][t] = oi[t];
#pragma unroll
            for (int t = 0; t < QC; t++) s_c[tid][t] = oc[t];
        }
        __syncthreads();
    }

    if (tid == 0) {
        float sum = 0.0f;
        for (int j = 0; j < QI; j++) sum += s_i[0][j];   // descending == top_k order
        int k = (int)sum;            // astype(int32): truncate toward zero
        if (k < 1)  k = 1;           // clip(., 1, P)
        if (k > QC) k = QC;          // provably <= 9
        int enc = mask_is_word(masks);
        if (!mask_at(masks, enc, bg)) k = 0;   // invalid gt selects nothing
        int b = bg / GG;
        unsigned int g = (unsigned int)(bg % GG);
        for (int j = 0; j < k; j++) {
            unsigned long long key = s_c[0][j];
            int p = (int)(key & 0xFFFFFFFFull);
            unsigned int ck = (unsigned int)(key >> 32);
            if (ck != 0xFFFFFFFFu) {
                unsigned long long akey = ((unsigned long long)ck << 32) | g;
                atomicMin(&g_akey[b * PP + p], akey);   // fire-and-forget RED
            }
        }
    }
}

// ---------------------------------------------------------------------------
// Kernel 3: fully-parallel output writer.
// ---------------------------------------------------------------------------
__global__ __launch_bounds__(256) void output_kernel(float* __restrict__ out)
{
    int i = blockIdx.x * 256 + threadIdx.x;        // i in [0, BB*PP)
    unsigned long long key = g_akey[i];
    bool matched = (key != 0xFFFFFFFFFFFFFFFFull);
    int g = (int)(key & 0xFFFFFFFFull);
    out[i] = matched ? 1.0f : 0.0f;                        // assigned_mask
    out[BB * PP + i] = matched ? (float)g : -1.0f;         // matched
}

// ---------------------------------------------------------------------------
extern "C" void kernel_launch(void* const* d_in, const int* in_sizes, int n_in,
                              void* d_out, int out_size)
{
    const float* preds   = (const float*)d_in[0];
    const float* targets = (const float*)d_in[1];
    const unsigned char* masks = (const unsigned char*)d_in[2];
    const int* imgw = (n_in > 3) ? (const int*)d_in[3] : nullptr;

    cost_kernel<<<dim3(PP / 128, BB, GZ), 128>>>(preds, targets, masks, imgw);
    select_kernel<<<BB * GG, 256>>>(masks);
    output_kernel<<<(BB * PP) / 256, 256>>>((float*)d_out);
}